// round 2
// baseline (speedup 1.0000x reference)
#include <cuda_runtime.h>

#define N_NODES 8192
#define F_DIM   128
#define TI      64      // rows per block in attention kernel
#define JT      32      // j-chunk
#define ALPHA_S 0.2f

// ---- scratch (no allocations allowed) ----
__device__ float g_h[N_NODES * F_DIM];     // h = x * W
__device__ float g_f1[N_NODES];
__device__ float g_f2[N_NODES];
__device__ float g_e1p[N_NODES];           // exp(f1)
__device__ float g_e1m[N_NODES];           // exp(alpha*f1)
__device__ float g_e2p[N_NODES];           // exp(f2)
__device__ float g_e2m[N_NODES];           // exp(alpha*f2)
__device__ float g_r[N_NODES];             // adj @ W2

// ---------------------------------------------------------------------------
// Kernel 1: h = x*W ; f1 = h@a[:F] ; f2 = h@a[F:] ; precompute 4 exp arrays.
// One block (128 threads) per row.
// ---------------------------------------------------------------------------
__global__ void prep_kernel(const float* __restrict__ x,
                            const float* __restrict__ W,
                            const float* __restrict__ a) {
    int i = blockIdx.x;
    int f = threadIdx.x;
    float hv = x[i * F_DIM + f] * W[i * F_DIM + f];
    g_h[i * F_DIM + f] = hv;

    float p1 = hv * a[f];
    float p2 = hv * a[F_DIM + f];
    #pragma unroll
    for (int off = 16; off; off >>= 1) {
        p1 += __shfl_down_sync(0xffffffffu, p1, off);
        p2 += __shfl_down_sync(0xffffffffu, p2, off);
    }
    __shared__ float s1[4], s2[4];
    int lane = f & 31, wid = f >> 5;
    if (lane == 0) { s1[wid] = p1; s2[wid] = p2; }
    __syncthreads();
    if (f == 0) {
        float f1v = s1[0] + s1[1] + s1[2] + s1[3];
        float f2v = s2[0] + s2[1] + s2[2] + s2[3];
        g_f1[i] = f1v;
        g_f2[i] = f2v;
        g_e1p[i] = expf(f1v);
        g_e1m[i] = expf(ALPHA_S * f1v);
        g_e2p[i] = expf(f2v);
        g_e2m[i] = expf(ALPHA_S * f2v);
    }
}

// ---------------------------------------------------------------------------
// Kernel 2: fused masked-softmax attention GEMM + r = adj @ W2.
//   W_ij = adj_ij * ((f1_i+f2_j >= 0) ? e1p_i*e2p_j : e1m_i*e2m_j)
//   h_prime[i,:] = (sum_j W_ij * h[j,:]) / (sum_j W_ij)
// Block: 256 threads = (32 f-lanes) x (8 warps). Each warp owns 8 rows.
// Each thread: acc[8 rows][4 cols], i.e. cols f = tx*4..tx*4+3.
// adj is read exactly once (streamed), also feeding r.
// ---------------------------------------------------------------------------
__global__ __launch_bounds__(256) void attn_kernel(const int* __restrict__ adj,
                                                   const float* __restrict__ W2,
                                                   float* __restrict__ hp) {
    int i0 = blockIdx.x * TI;
    int tx = threadIdx.x & 31;   // f-group index / j lane
    int w  = threadIdx.x >> 5;   // warp id 0..7 -> rows i0 + w*8 + k

    __shared__ float h_s[JT][F_DIM];
    __shared__ float W_s[TI][JT];

    float acc[8][4];
    float zp[8], rp[8];
    #pragma unroll
    for (int k = 0; k < 8; k++) {
        zp[k] = 0.f; rp[k] = 0.f;
        acc[k][0] = acc[k][1] = acc[k][2] = acc[k][3] = 0.f;
    }

    // per-row constants (fixed for the whole kernel)
    float f1r[8], e1pr[8], e1mr[8];
    #pragma unroll
    for (int k = 0; k < 8; k++) {
        int row = i0 + w * 8 + k;
        f1r[k]  = g_f1[row];
        e1pr[k] = g_e1p[row];
        e1mr[k] = g_e1m[row];
    }

    // --- software pipeline: preload chunk 0 (adj + h + j-constants) ---
    int   av[8];
    float f2v, e2pv, e2mv, w2v;
    float4 hreg[4];
    {
        int j = tx;
        f2v  = g_f2[j];  e2pv = g_e2p[j];  e2mv = g_e2m[j];  w2v = W2[j];
        #pragma unroll
        for (int k = 0; k < 8; k++)
            av[k] = __ldcs(&adj[(i0 + w * 8 + k) * N_NODES + j]);
        #pragma unroll
        for (int t = 0; t < 4; t++) {
            int p = threadIdx.x + t * 256;
            int row = p >> 5, c4 = p & 31;
            hreg[t] = *(const float4*)&g_h[row * F_DIM + c4 * 4];
        }
    }

    for (int j0 = 0; j0 < N_NODES; j0 += JT) {
        // stage h tile from prefetched regs
        #pragma unroll
        for (int t = 0; t < 4; t++) {
            int p = threadIdx.x + t * 256;
            int row = p >> 5, c4 = p & 31;
            *(float4*)&h_s[row][c4 * 4] = hreg[t];
        }
        // build coefficient tile + Z and r accumulation
        #pragma unroll
        for (int k = 0; k < 8; k++) {
            float s  = f1r[k] + f2v;
            float wv = (s >= 0.f) ? e1pr[k] * e2pv : e1mr[k] * e2mv;
            wv = av[k] ? wv : 0.f;
            W_s[w * 8 + k][tx] = wv;
            zp[k] += wv;
            if (av[k]) rp[k] += w2v;
        }
        // prefetch next chunk (overlaps with GEMM below)
        int j1 = j0 + JT;
        if (j1 < N_NODES) {
            int j = j1 + tx;
            f2v  = g_f2[j];  e2pv = g_e2p[j];  e2mv = g_e2m[j];  w2v = W2[j];
            #pragma unroll
            for (int k = 0; k < 8; k++)
                av[k] = __ldcs(&adj[(i0 + w * 8 + k) * N_NODES + j]);
            #pragma unroll
            for (int t = 0; t < 4; t++) {
                int p = threadIdx.x + t * 256;
                int row = p >> 5, c4 = p & 31;
                hreg[t] = *(const float4*)&g_h[(j1 + row) * F_DIM + c4 * 4];
            }
        }
        __syncthreads();
        // register-blocked GEMM on the tile
        #pragma unroll 8
        for (int jj = 0; jj < JT; jj++) {
            float4 hv = *(const float4*)&h_s[jj][tx * 4];
            #pragma unroll
            for (int k = 0; k < 8; k++) {
                float wv = W_s[w * 8 + k][jj];
                acc[k][0] += wv * hv.x;
                acc[k][1] += wv * hv.y;
                acc[k][2] += wv * hv.z;
                acc[k][3] += wv * hv.w;
            }
        }
        __syncthreads();
    }

    // reduce Z and r across the 32 lanes (each lane covered j = lane mod 32)
    #pragma unroll
    for (int k = 0; k < 8; k++) {
        #pragma unroll
        for (int off = 16; off; off >>= 1) {
            zp[k] += __shfl_xor_sync(0xffffffffu, zp[k], off);
            rp[k] += __shfl_xor_sync(0xffffffffu, rp[k], off);
        }
    }
    if (tx == 0) {
        #pragma unroll
        for (int k = 0; k < 8; k++)
            g_r[i0 + w * 8 + k] = rp[k];
    }
    // write h_prime = acc / Z
    #pragma unroll
    for (int k = 0; k < 8; k++) {
        float inv = 1.0f / zp[k];
        float4 o;
        o.x = acc[k][0] * inv;
        o.y = acc[k][1] * inv;
        o.z = acc[k][2] * inv;
        o.w = acc[k][3] * inv;
        *(float4*)&hp[(i0 + w * 8 + k) * F_DIM + tx * 4] = o;
    }
}

// ---------------------------------------------------------------------------
// Kernel 3: out[f] = elu( sum_i r[i] * x[i,f] ).  One block per f.
// ---------------------------------------------------------------------------
__global__ void out_kernel(const float* __restrict__ x,
                           float* __restrict__ out) {
    int f = blockIdx.x;
    float p = 0.f;
    for (int i = threadIdx.x; i < N_NODES; i += 256)
        p += g_r[i] * x[i * F_DIM + f];
    #pragma unroll
    for (int off = 16; off; off >>= 1)
        p += __shfl_xor_sync(0xffffffffu, p, off);
    __shared__ float s[8];
    int lane = threadIdx.x & 31, wid = threadIdx.x >> 5;
    if (lane == 0) s[wid] = p;
    __syncthreads();
    if (threadIdx.x == 0) {
        float v = 0.f;
        #pragma unroll
        for (int k = 0; k < 8; k++) v += s[k];
        out[f] = (v > 0.f) ? v : (expf(v) - 1.0f);
    }
}

// ---------------------------------------------------------------------------
extern "C" void kernel_launch(void* const* d_in, const int* in_sizes, int n_in,
                              void* d_out, int out_size) {
    const float* x   = (const float*)d_in[0];
    const int*   adj = (const int*)  d_in[1];
    const float* W   = (const float*)d_in[2];
    const float* a   = (const float*)d_in[3];
    const float* W2  = (const float*)d_in[4];
    float* out = (float*)d_out;                 // [0:128) = elu output, [128:) = h_prime

    prep_kernel<<<N_NODES, F_DIM>>>(x, W, a);
    attn_kernel<<<N_NODES / TI, 256>>>(adj, W2, out + F_DIM);
    out_kernel<<<F_DIM, 256>>>(x, out);
}

// round 4
// speedup vs baseline: 1.3697x; 1.3697x over previous
#include <cuda_runtime.h>
#include <cstdint>
#include <cstddef>

#define N_NODES 8192
#define F_DIM   128
#define KC      32
#define NCHUNK  256
#define M_CTA   64

// dynamic smem layout (float offsets)
#define A_F(b)   ((b)*2304)            // A tile [64][36] padded
#define B_F(b)   (4608 + (b)*4352)     // B tile [32][136] padded
#define Z_F      13312                 // z[64]
#define DYN_SMEM 53504                 // (13312+64)*4 bytes

// ---- scratch ----
__device__ float  g_h [N_NODES * F_DIM];
__device__ float  g_q [N_NODES];          // exp(0.8*f1)
__device__ float4 g_jc[N_NODES];          // {exp(f2), exp(0.2*f2), W2, 0}
__device__ float  g_r [N_NODES];          // adj @ W2

// ===================== helpers =====================
__device__ __forceinline__ uint32_t smem_u32(const void* p) {
    uint32_t a;
    asm("{ .reg .u64 t; cvta.to.shared.u64 t, %1; cvt.u32.u64 %0, t; }" : "=r"(a) : "l"(p));
    return a;
}
__device__ __forceinline__ uint32_t f2tf(float v) {
    uint32_t o;
    asm("cvt.rna.tf32.f32 %0, %1;" : "=r"(o) : "f"(v));
    return o;
}
__device__ __forceinline__ void mma8(float* d, const uint32_t* a, const uint32_t* b) {
    asm volatile("mma.sync.aligned.m16n8k8.row.col.f32.tf32.tf32.f32 "
        "{%0,%1,%2,%3}, {%4,%5,%6,%7}, {%8,%9}, {%0,%1,%2,%3};"
        : "+f"(d[0]), "+f"(d[1]), "+f"(d[2]), "+f"(d[3])
        : "r"(a[0]), "r"(a[1]), "r"(a[2]), "r"(a[3]), "r"(b[0]), "r"(b[1]));
}
__device__ __forceinline__ void cp16(uint32_t daddr, const void* gsrc) {
    asm volatile("cp.async.cg.shared.global [%0], [%1], 16;"
                 :: "r"(daddr), "l"(gsrc) : "memory");
}

// ===================== Kernel 1: prep =====================
__global__ __launch_bounds__(256) void prep_kernel(const float* __restrict__ x,
                                                   const float* __restrict__ W,
                                                   const float* __restrict__ a,
                                                   const float* __restrict__ W2) {
    int wid = threadIdx.x >> 5, lane = threadIdx.x & 31;
    int i = blockIdx.x * 8 + wid;
    float4 xv = *(const float4*)&x[(size_t)i * F_DIM + lane * 4];
    float4 wv = *(const float4*)&W[(size_t)i * F_DIM + lane * 4];
    float4 h;
    h.x = xv.x * wv.x; h.y = xv.y * wv.y; h.z = xv.z * wv.z; h.w = xv.w * wv.w;
    *(float4*)&g_h[(size_t)i * F_DIM + lane * 4] = h;
    float4 a1 = *(const float4*)&a[lane * 4];
    float4 a2 = *(const float4*)&a[F_DIM + lane * 4];
    float p1 = h.x * a1.x + h.y * a1.y + h.z * a1.z + h.w * a1.w;
    float p2 = h.x * a2.x + h.y * a2.y + h.z * a2.z + h.w * a2.w;
    #pragma unroll
    for (int off = 16; off; off >>= 1) {
        p1 += __shfl_xor_sync(0xffffffffu, p1, off);
        p2 += __shfl_xor_sync(0xffffffffu, p2, off);
    }
    if (lane == 0) {
        g_q[i] = expf(0.8f * p1);
        float4 jc;
        jc.x = expf(p2);
        jc.y = expf(0.2f * p2);
        jc.z = W2[i];
        jc.w = 0.f;
        g_jc[i] = jc;
    }
}

// ===================== Kernel 2: mma.sync tf32 attention =====================
// Grid 128 CTAs (64 i-rows each), 128 threads (4 warps).
// warp tile 32x64: mw = wid&1 (M band), nw = wid>>1 (N band).
__global__ __launch_bounds__(128, 1) void attn_kernel(const int* __restrict__ adj,
                                                      float* __restrict__ hp) {
    extern __shared__ float sm[];
    int tid = threadIdx.x, wid = tid >> 5, lane = tid & 31;
    int gl = lane >> 2, ql = lane & 3;
    int i0 = blockIdx.x * M_CTA;
    int mw = wid & 1, nw = wid >> 1;

    // ---- per-build-row state: warp owns rows wid*16 .. +15, lane = k-col ----
    float pi[16], zp[16], rp[16];
    const int* ap = adj + (size_t)(i0 + wid * 16) * N_NODES + lane;
    #pragma unroll
    for (int k = 0; k < 16; k++) {
        pi[k] = g_q[i0 + wid * 16 + k];
        zp[k] = 0.f; rp[k] = 0.f;
    }

    float acc[2][8][4];
    #pragma unroll
    for (int mt = 0; mt < 2; mt++)
        #pragma unroll
        for (int nt = 0; nt < 8; nt++)
            acc[mt][nt][0] = acc[mt][nt][1] = acc[mt][nt][2] = acc[mt][nt][3] = 0.f;

    // ---- prefetch chunk 0 ----
    int av[16]; float4 jc;
    jc = g_jc[lane];
    #pragma unroll
    for (int k = 0; k < 16; k++) av[k] = __ldcs(ap + (size_t)k * N_NODES);
    #pragma unroll
    for (int p = 0; p < 8; p++) {
        int idx = tid + p * 128, row = idx >> 5, f4 = idx & 31;
        cp16(smem_u32(&sm[B_F(0) + row * 136 + f4 * 4]),
             &g_h[(size_t)row * F_DIM + f4 * 4]);
    }
    asm volatile("cp.async.commit_group;" ::: "memory");

    for (int c = 0; c < NCHUNK; c++) {
        int b = c & 1;
        // ---- build A tile (tf32-rounded w') + z/r accumulation ----
        #pragma unroll
        for (int k = 0; k < 16; k++) {
            float wv = av[k] ? fmaxf(pi[k] * jc.x, jc.y) : 0.f;
            zp[k] += wv;
            rp[k] += av[k] ? jc.z : 0.f;
            sm[A_F(b) + (wid * 16 + k) * 36 + lane] = __uint_as_float(f2tf(wv));
        }
        // ---- register-prefetch adj/jc for chunk c+1 ----
        if (c + 1 < NCHUNK) {
            jc = g_jc[(c + 1) * KC + lane];
            const int* ap2 = ap + (c + 1) * KC;
            #pragma unroll
            for (int k = 0; k < 16; k++) av[k] = __ldcs(ap2 + (size_t)k * N_NODES);
        }
        asm volatile("cp.async.wait_group 0;" ::: "memory");  // B(c) landed
        __syncthreads();                                      // A(c) visible, old LDS drained
        // ---- issue cp.async for B(c+1) (overlaps mma below) ----
        if (c + 1 < NCHUNK) {
            #pragma unroll
            for (int p = 0; p < 8; p++) {
                int idx = tid + p * 128, row = idx >> 5, f4 = idx & 31;
                cp16(smem_u32(&sm[B_F(b ^ 1) + row * 136 + f4 * 4]),
                     &g_h[(size_t)((c + 1) * KC + row) * F_DIM + f4 * 4]);
            }
            asm volatile("cp.async.commit_group;" ::: "memory");
        }
        // ---- mma on buffer b ----
        const float* Ab = &sm[A_F(b)];
        const float* Bb = &sm[B_F(b)];
        #pragma unroll
        for (int s = 0; s < 4; s++) {
            int k0 = s * 8;
            uint32_t afr[2][4];
            #pragma unroll
            for (int mt = 0; mt < 2; mt++) {
                int r0 = mw * 32 + mt * 16 + gl;
                afr[mt][0] = __float_as_uint(Ab[r0 * 36 + k0 + ql]);
                afr[mt][1] = __float_as_uint(Ab[(r0 + 8) * 36 + k0 + ql]);
                afr[mt][2] = __float_as_uint(Ab[r0 * 36 + k0 + ql + 4]);
                afr[mt][3] = __float_as_uint(Ab[(r0 + 8) * 36 + k0 + ql + 4]);
            }
            #pragma unroll
            for (int nt = 0; nt < 8; nt++) {
                int col = nw * 64 + nt * 8 + gl;
                uint32_t bfr[2];
                bfr[0] = f2tf(Bb[(k0 + ql) * 136 + col]);
                bfr[1] = f2tf(Bb[(k0 + ql + 4) * 136 + col]);
                mma8(acc[0][nt], afr[0], bfr);
                mma8(acc[1][nt], afr[1], bfr);
            }
        }
    }

    // ---- reduce z and r across lanes (lane l covered j === l mod 32) ----
    #pragma unroll
    for (int k = 0; k < 16; k++) {
        float z = zp[k], r = rp[k];
        #pragma unroll
        for (int off = 16; off; off >>= 1) {
            z += __shfl_xor_sync(0xffffffffu, z, off);
            r += __shfl_xor_sync(0xffffffffu, r, off);
        }
        zp[k] = z; rp[k] = r;
    }
    if (lane == 0) {
        #pragma unroll
        for (int k = 0; k < 16; k++) {
            sm[Z_F + wid * 16 + k] = zp[k];
            g_r[i0 + wid * 16 + k] = rp[k];
        }
    }
    __syncthreads();

    // ---- epilogue: divide by z, write h_prime ----
    #pragma unroll
    for (int mt = 0; mt < 2; mt++) {
        int r0 = mw * 32 + mt * 16 + gl;
        float inv0 = 1.0f / sm[Z_F + r0];
        float inv1 = 1.0f / sm[Z_F + r0 + 8];
        #pragma unroll
        for (int nt = 0; nt < 8; nt++) {
            int col = nw * 64 + nt * 8 + ql * 2;
            float2 v0 = make_float2(acc[mt][nt][0] * inv0, acc[mt][nt][1] * inv0);
            float2 v1 = make_float2(acc[mt][nt][2] * inv1, acc[mt][nt][3] * inv1);
            *(float2*)&hp[(size_t)(i0 + r0) * F_DIM + col] = v0;
            *(float2*)&hp[(size_t)(i0 + r0 + 8) * F_DIM + col] = v1;
        }
    }
}

// ===================== Kernel 3: out = elu(r^T @ x) =====================
__global__ void out_kernel(const float* __restrict__ x, float* __restrict__ out) {
    int f = blockIdx.x;
    float p = 0.f;
    for (int i = threadIdx.x; i < N_NODES; i += 256)
        p += g_r[i] * x[(size_t)i * F_DIM + f];
    #pragma unroll
    for (int off = 16; off; off >>= 1)
        p += __shfl_xor_sync(0xffffffffu, p, off);
    __shared__ float s[8];
    int lane = threadIdx.x & 31, wid = threadIdx.x >> 5;
    if (lane == 0) s[wid] = p;
    __syncthreads();
    if (threadIdx.x == 0) {
        float v = 0.f;
        #pragma unroll
        for (int k = 0; k < 8; k++) v += s[k];
        out[f] = (v > 0.f) ? v : (expf(v) - 1.0f);
    }
}

// ===========================================================================
extern "C" void kernel_launch(void* const* d_in, const int* in_sizes, int n_in,
                              void* d_out, int out_size) {
    const float* x   = (const float*)d_in[0];
    const int*   adj = (const int*)  d_in[1];
    const float* W   = (const float*)d_in[2];
    const float* a   = (const float*)d_in[3];
    const float* W2  = (const float*)d_in[4];
    float* out = (float*)d_out;   // [0:128) elu output, [128:) h_prime

    cudaFuncSetAttribute(attn_kernel, cudaFuncAttributeMaxDynamicSharedMemorySize, DYN_SMEM);

    prep_kernel<<<N_NODES / 8, 256>>>(x, W, a, W2);
    attn_kernel<<<N_NODES / M_CTA, 128, DYN_SMEM>>>(adj, out + F_DIM);
    out_kernel<<<F_DIM, 256>>>(x, out);
}

// round 5
// speedup vs baseline: 1.8603x; 1.3582x over previous
#include <cuda_runtime.h>
#include <cstdint>
#include <cstddef>

#define N_NODES 8192
#define F_DIM   128
#define KC      32
#define NCHUNK  256
#define M_CTA   64

// dynamic smem layout (float offsets)
#define A_F(b)   ((b)*2304)            // A tile [64][36] padded
#define B_F(b)   (4608 + (b)*4352)     // B tile [32][136] padded
#define Z_F      13312                 // z[64]
#define DYN_SMEM 53504

// ---- scratch ----
__device__ float  g_h [N_NODES * F_DIM];  // tf32-rounded h (valid fp32 bit patterns)
__device__ float  g_q [N_NODES];          // exp(0.8*f1)
__device__ float4 g_jc[N_NODES];          // {exp(f2), exp(0.2*f2), W2, 0}
__device__ float  g_r [N_NODES];          // adj @ W2

// ===================== helpers =====================
__device__ __forceinline__ uint32_t smem_u32(const void* p) {
    uint32_t a;
    asm("{ .reg .u64 t; cvta.to.shared.u64 t, %1; cvt.u32.u64 %0, t; }" : "=r"(a) : "l"(p));
    return a;
}
__device__ __forceinline__ uint32_t f2tf(float v) {
    uint32_t o;
    asm("cvt.rna.tf32.f32 %0, %1;" : "=r"(o) : "f"(v));
    return o;
}
__device__ __forceinline__ void mma8(float* d, const uint32_t* a, const uint32_t* b) {
    asm volatile("mma.sync.aligned.m16n8k8.row.col.f32.tf32.tf32.f32 "
        "{%0,%1,%2,%3}, {%4,%5,%6,%7}, {%8,%9}, {%0,%1,%2,%3};"
        : "+f"(d[0]), "+f"(d[1]), "+f"(d[2]), "+f"(d[3])
        : "r"(a[0]), "r"(a[1]), "r"(a[2]), "r"(a[3]), "r"(b[0]), "r"(b[1]));
}
__device__ __forceinline__ void cp16(uint32_t daddr, const void* gsrc) {
    asm volatile("cp.async.cg.shared.global [%0], [%1], 16;"
                 :: "r"(daddr), "l"(gsrc) : "memory");
}

// ===================== Kernel 1: prep =====================
__global__ __launch_bounds__(256) void prep_kernel(const float* __restrict__ x,
                                                   const float* __restrict__ W,
                                                   const float* __restrict__ a,
                                                   const float* __restrict__ W2) {
    int wid = threadIdx.x >> 5, lane = threadIdx.x & 31;
    int i = blockIdx.x * 8 + wid;
    float4 xv = *(const float4*)&x[(size_t)i * F_DIM + lane * 4];
    float4 wv = *(const float4*)&W[(size_t)i * F_DIM + lane * 4];
    float4 h;
    h.x = xv.x * wv.x; h.y = xv.y * wv.y; h.z = xv.z * wv.z; h.w = xv.w * wv.w;
    // store tf32-rounded h (mma B operand needs no cvt at load time)
    float4 ht;
    ht.x = __uint_as_float(f2tf(h.x));
    ht.y = __uint_as_float(f2tf(h.y));
    ht.z = __uint_as_float(f2tf(h.z));
    ht.w = __uint_as_float(f2tf(h.w));
    *(float4*)&g_h[(size_t)i * F_DIM + lane * 4] = ht;

    float4 a1 = *(const float4*)&a[lane * 4];
    float4 a2 = *(const float4*)&a[F_DIM + lane * 4];
    float p1 = h.x * a1.x + h.y * a1.y + h.z * a1.z + h.w * a1.w;
    float p2 = h.x * a2.x + h.y * a2.y + h.z * a2.z + h.w * a2.w;
    #pragma unroll
    for (int off = 16; off; off >>= 1) {
        p1 += __shfl_xor_sync(0xffffffffu, p1, off);
        p2 += __shfl_xor_sync(0xffffffffu, p2, off);
    }
    if (lane == 0) {
        g_q[i] = expf(0.8f * p1);
        float4 jc;
        jc.x = expf(p2);
        jc.y = expf(0.2f * p2);
        jc.z = W2[i];
        jc.w = 0.f;
        g_jc[i] = jc;
    }
}

// ===================== Kernel 2: mma.sync tf32 attention =====================
// Grid 128 CTAs (64 i-rows each), 256 threads (8 warps, 2/SMSP).
// Warp tile 32x32: mw = wid&1 (M band), nw = wid>>1 (N band 0..3).
__global__ __launch_bounds__(256, 1) void attn_kernel(const int* __restrict__ adj,
                                                      float* __restrict__ hp) {
    extern __shared__ float sm[];
    int tid = threadIdx.x, wid = tid >> 5, lane = tid & 31;
    int gl = lane >> 2, ql = lane & 3;
    int i0 = blockIdx.x * M_CTA;
    int mw = wid & 1, nw = wid >> 1;

    // ---- build state: warp owns rows wid*8 .. +7, lane = j-offset ----
    float pi[8], zp[8], rp[8];
    const int* ap = adj + (size_t)(i0 + wid * 8) * N_NODES + lane;
    #pragma unroll
    for (int k = 0; k < 8; k++) {
        pi[k] = g_q[i0 + wid * 8 + k];
        zp[k] = 0.f; rp[k] = 0.f;
    }

    float acc[2][4][4];
    #pragma unroll
    for (int mt = 0; mt < 2; mt++)
        #pragma unroll
        for (int nt = 0; nt < 4; nt++)
            acc[mt][nt][0] = acc[mt][nt][1] = acc[mt][nt][2] = acc[mt][nt][3] = 0.f;

    // ---- prefetch chunk 0 ----
    int av[8]; float4 jc;
    jc = g_jc[lane];
    #pragma unroll
    for (int k = 0; k < 8; k++) av[k] = __ldcs(ap + (size_t)k * N_NODES);
    #pragma unroll
    for (int p = 0; p < 4; p++) {
        int idx = tid + p * 256, row = idx >> 5, f4 = idx & 31;
        cp16(smem_u32(&sm[B_F(0) + row * 136 + f4 * 4]),
             &g_h[(size_t)row * F_DIM + f4 * 4]);
    }
    asm volatile("cp.async.commit_group;" ::: "memory");

    for (int c = 0; c < NCHUNK; c++) {
        int b = c & 1;
        // ---- build A tile (tf32-rounded w') + z/r accumulation ----
        #pragma unroll
        for (int k = 0; k < 8; k++) {
            float wv = av[k] ? fmaxf(pi[k] * jc.x, jc.y) : 0.f;
            zp[k] += wv;
            rp[k] += av[k] ? jc.z : 0.f;
            sm[A_F(b) + (wid * 8 + k) * 36 + lane] = __uint_as_float(f2tf(wv));
        }
        // ---- register-prefetch adj/jc for chunk c+1 ----
        if (c + 1 < NCHUNK) {
            jc = g_jc[(c + 1) * KC + lane];
            const int* ap2 = ap + (c + 1) * KC;
            #pragma unroll
            for (int k = 0; k < 8; k++) av[k] = __ldcs(ap2 + (size_t)k * N_NODES);
        }
        asm volatile("cp.async.wait_group 0;" ::: "memory");  // B(c) landed
        __syncthreads();                                      // A(c) visible
        // ---- issue cp.async for B(c+1) (overlaps mma below) ----
        if (c + 1 < NCHUNK) {
            #pragma unroll
            for (int p = 0; p < 4; p++) {
                int idx = tid + p * 256, row = idx >> 5, f4 = idx & 31;
                cp16(smem_u32(&sm[B_F(b ^ 1) + row * 136 + f4 * 4]),
                     &g_h[(size_t)((c + 1) * KC + row) * F_DIM + f4 * 4]);
            }
            asm volatile("cp.async.commit_group;" ::: "memory");
        }
        // ---- mma on buffer b ----
        const float* Ab = &sm[A_F(b)];
        const float* Bb = &sm[B_F(b)];
        #pragma unroll
        for (int s = 0; s < 4; s++) {
            int k0 = s * 8;
            uint32_t afr[2][4];
            #pragma unroll
            for (int mt = 0; mt < 2; mt++) {
                int r0 = mw * 32 + mt * 16 + gl;
                afr[mt][0] = __float_as_uint(Ab[r0 * 36 + k0 + ql]);
                afr[mt][1] = __float_as_uint(Ab[(r0 + 8) * 36 + k0 + ql]);
                afr[mt][2] = __float_as_uint(Ab[r0 * 36 + k0 + ql + 4]);
                afr[mt][3] = __float_as_uint(Ab[(r0 + 8) * 36 + k0 + ql + 4]);
            }
            #pragma unroll
            for (int nt = 0; nt < 4; nt++) {
                int col = nw * 32 + nt * 8 + gl;
                uint32_t bfr[2];
                bfr[0] = __float_as_uint(Bb[(k0 + ql) * 136 + col]);
                bfr[1] = __float_as_uint(Bb[(k0 + ql + 4) * 136 + col]);
                mma8(acc[0][nt], afr[0], bfr);
                mma8(acc[1][nt], afr[1], bfr);
            }
        }
    }

    // ---- reduce z and r across lanes (lane l covered j === l mod 32) ----
    #pragma unroll
    for (int k = 0; k < 8; k++) {
        float z = zp[k], r = rp[k];
        #pragma unroll
        for (int off = 16; off; off >>= 1) {
            z += __shfl_xor_sync(0xffffffffu, z, off);
            r += __shfl_xor_sync(0xffffffffu, r, off);
        }
        zp[k] = z; rp[k] = r;
    }
    if (lane == 0) {
        #pragma unroll
        for (int k = 0; k < 8; k++) {
            sm[Z_F + wid * 8 + k] = zp[k];
            g_r[i0 + wid * 8 + k] = rp[k];
        }
    }
    __syncthreads();

    // ---- epilogue: divide by z, write h_prime ----
    #pragma unroll
    for (int mt = 0; mt < 2; mt++) {
        int r0 = mw * 32 + mt * 16 + gl;
        float inv0 = 1.0f / sm[Z_F + r0];
        float inv1 = 1.0f / sm[Z_F + r0 + 8];
        #pragma unroll
        for (int nt = 0; nt < 4; nt++) {
            int col = nw * 32 + nt * 8 + ql * 2;
            float2 v0 = make_float2(acc[mt][nt][0] * inv0, acc[mt][nt][1] * inv0);
            float2 v1 = make_float2(acc[mt][nt][2] * inv1, acc[mt][nt][3] * inv1);
            *(float2*)&hp[(size_t)(i0 + r0) * F_DIM + col] = v0;
            *(float2*)&hp[(size_t)(i0 + r0 + 8) * F_DIM + col] = v1;
        }
    }
}

// ===================== Kernel 3: out = elu(r^T @ x) =====================
__global__ void out_kernel(const float* __restrict__ x, float* __restrict__ out) {
    int f = blockIdx.x;
    float p = 0.f;
    for (int i = threadIdx.x; i < N_NODES; i += 256)
        p += g_r[i] * x[(size_t)i * F_DIM + f];
    #pragma unroll
    for (int off = 16; off; off >>= 1)
        p += __shfl_xor_sync(0xffffffffu, p, off);
    __shared__ float s[8];
    int lane = threadIdx.x & 31, wid = threadIdx.x >> 5;
    if (lane == 0) s[wid] = p;
    __syncthreads();
    if (threadIdx.x == 0) {
        float v = 0.f;
        #pragma unroll
        for (int k = 0; k < 8; k++) v += s[k];
        out[f] = (v > 0.f) ? v : (expf(v) - 1.0f);
    }
}

// ===========================================================================
extern "C" void kernel_launch(void* const* d_in, const int* in_sizes, int n_in,
                              void* d_out, int out_size) {
    const float* x   = (const float*)d_in[0];
    const int*   adj = (const int*)  d_in[1];
    const float* W   = (const float*)d_in[2];
    const float* a   = (const float*)d_in[3];
    const float* W2  = (const float*)d_in[4];
    float* out = (float*)d_out;   // [0:128) elu output, [128:) h_prime

    cudaFuncSetAttribute(attn_kernel, cudaFuncAttributeMaxDynamicSharedMemorySize, DYN_SMEM);

    prep_kernel<<<N_NODES / 8, 256>>>(x, W, a, W2);
    attn_kernel<<<N_NODES / M_CTA, 256, DYN_SMEM>>>(adj, out + F_DIM);
    out_kernel<<<F_DIM, 256>>>(x, out);
}

// round 6
// speedup vs baseline: 3.0317x; 1.6296x over previous
#include <cuda_runtime.h>
#include <cuda_fp16.h>
#include <cstdint>
#include <cstddef>

#define N_NODES 8192
#define F_DIM   128
#define KC      32
#define NCHUNK  256
#define M_CTA   32

// smem byte layout: A[2][32][40]h, B[3][128][40]h, Z[32]f
#define A_OFF(b)  ((b) * 2560)
#define B_OFF(b)  (5120 + (b) * 10240)
#define Z_OFF     35840
#define DYN_SMEM  36992

// ---- scratch ----
__device__ float    g_h  [N_NODES * F_DIM];            // h fp32 [i][f]
__device__ __half   g_hT [(size_t)F_DIM * N_NODES];    // h fp16 transposed [f][j]
__device__ float    g_q  [N_NODES];                    // exp(0.8*f1)
__device__ float4   g_jc [N_NODES];                    // {exp(f2), exp(0.2*f2), W2, 0}
__device__ uint32_t g_ab [N_NODES * NCHUNK];           // adjacency bitmask
__device__ float    g_r  [N_NODES];                    // adj @ W2

// ===================== helpers =====================
__device__ __forceinline__ uint32_t smem_u32(const void* p) {
    uint32_t a;
    asm("{ .reg .u64 t; cvta.to.shared.u64 t, %1; cvt.u32.u64 %0, t; }" : "=r"(a) : "l"(p));
    return a;
}
__device__ __forceinline__ void mma16(float* d, const uint32_t* a, const uint32_t* b) {
    asm volatile("mma.sync.aligned.m16n8k16.row.col.f32.f16.f16.f32 "
        "{%0,%1,%2,%3}, {%4,%5,%6,%7}, {%8,%9}, {%0,%1,%2,%3};"
        : "+f"(d[0]), "+f"(d[1]), "+f"(d[2]), "+f"(d[3])
        : "r"(a[0]), "r"(a[1]), "r"(a[2]), "r"(a[3]), "r"(b[0]), "r"(b[1]));
}
__device__ __forceinline__ void cp16(uint32_t daddr, const void* gsrc) {
    asm volatile("cp.async.cg.shared.global [%0], [%1], 16;"
                 :: "r"(daddr), "l"(gsrc) : "memory");
}

// ===================== Kernel 1: prep =====================
__global__ __launch_bounds__(256) void prep_kernel(const float* __restrict__ x,
                                                   const float* __restrict__ W,
                                                   const float* __restrict__ a,
                                                   const float* __restrict__ W2) {
    int wid = threadIdx.x >> 5, lane = threadIdx.x & 31;
    int i = blockIdx.x * 8 + wid;
    float4 xv = *(const float4*)&x[(size_t)i * F_DIM + lane * 4];
    float4 wv = *(const float4*)&W[(size_t)i * F_DIM + lane * 4];
    float4 h;
    h.x = xv.x * wv.x; h.y = xv.y * wv.y; h.z = xv.z * wv.z; h.w = xv.w * wv.w;
    *(float4*)&g_h[(size_t)i * F_DIM + lane * 4] = h;

    float4 a1 = *(const float4*)&a[lane * 4];
    float4 a2 = *(const float4*)&a[F_DIM + lane * 4];
    float p1 = h.x * a1.x + h.y * a1.y + h.z * a1.z + h.w * a1.w;
    float p2 = h.x * a2.x + h.y * a2.y + h.z * a2.z + h.w * a2.w;
    #pragma unroll
    for (int off = 16; off; off >>= 1) {
        p1 += __shfl_xor_sync(0xffffffffu, p1, off);
        p2 += __shfl_xor_sync(0xffffffffu, p2, off);
    }
    if (lane == 0) {
        g_q[i] = expf(0.8f * p1);
        float4 jc;
        jc.x = expf(p2);
        jc.y = expf(0.2f * p2);
        jc.z = W2[i];
        jc.w = 0.f;
        g_jc[i] = jc;
    }
}

// ===================== Kernel 2: pack adjacency into bitmask =====================
__global__ __launch_bounds__(256) void pack_kernel(const int* __restrict__ adj) {
    int wid = threadIdx.x >> 5, lane = threadIdx.x & 31;
    int row = blockIdx.x * 8 + wid;
    const int* ap = adj + (size_t)row * N_NODES + lane;
    #pragma unroll 1
    for (int c = 0; c < NCHUNK; c += 4) {
        int a0 = __ldcs(ap + (c + 0) * KC);
        int a1 = __ldcs(ap + (c + 1) * KC);
        int a2 = __ldcs(ap + (c + 2) * KC);
        int a3 = __ldcs(ap + (c + 3) * KC);
        uint32_t m0 = __ballot_sync(0xffffffffu, a0 != 0);
        uint32_t m1 = __ballot_sync(0xffffffffu, a1 != 0);
        uint32_t m2 = __ballot_sync(0xffffffffu, a2 != 0);
        uint32_t m3 = __ballot_sync(0xffffffffu, a3 != 0);
        if (lane == 0) {
            g_ab[row * NCHUNK + c + 0] = m0;
            g_ab[row * NCHUNK + c + 1] = m1;
            g_ab[row * NCHUNK + c + 2] = m2;
            g_ab[row * NCHUNK + c + 3] = m3;
        }
    }
}

// ===================== Kernel 3: transpose + fp16 convert =====================
__global__ __launch_bounds__(256) void transpose_kernel() {
    __shared__ float t[32][33];
    int j0 = blockIdx.x * 32, f0 = blockIdx.y * 32;
    int tx = threadIdx.x & 31, ty = threadIdx.x >> 5;
    #pragma unroll
    for (int k = 0; k < 4; k++)
        t[ty + k * 8][tx] = g_h[(size_t)(j0 + ty + k * 8) * F_DIM + f0 + tx];
    __syncthreads();
    #pragma unroll
    for (int k = 0; k < 4; k++)
        g_hT[(size_t)(f0 + ty + k * 8) * N_NODES + j0 + tx] = __float2half(t[tx][ty + k * 8]);
}

// ===================== Kernel 4: fp16 mma attention =====================
// Grid 256 CTAs (32 rows each), 256 threads (8 warps). Warp tile 16x32:
// mw = wid&1 (m-band), nw = wid>>1 (n-band 0..3).
__global__ __launch_bounds__(256, 2) void attn_kernel(float* __restrict__ hp) {
    extern __shared__ char smc[];
    uint32_t sb = smem_u32(smc);
    __half*   As16 = (__half*)smc;
    uint32_t* S32  = (uint32_t*)smc;
    float*    Zs   = (float*)(smc + Z_OFF);

    int tid = threadIdx.x, wid = tid >> 5, lane = tid & 31;
    int gl = lane >> 2, ql = lane & 3;
    int i0 = blockIdx.x * M_CTA;
    int mw = wid & 1, nw = wid >> 1;

    // build state: warp owns rows wid*4 .. +3; lane = j within chunk
    float pi[4], zp[4], rp[4];
    #pragma unroll
    for (int k = 0; k < 4; k++) {
        pi[k] = g_q[i0 + wid * 4 + k];
        zp[k] = 0.f; rp[k] = 0.f;
    }

    float acc[4][4];
    #pragma unroll
    for (int nt = 0; nt < 4; nt++)
        acc[nt][0] = acc[nt][1] = acc[nt][2] = acc[nt][3] = 0.f;

    // ---- prologue: prefetch chunk-0 scalars; issue B0, B1 ----
    uint32_t word = (lane < 4) ? g_ab[(i0 + wid * 4 + lane) * NCHUNK] : 0u;
    float4 jc = g_jc[lane];
    #pragma unroll
    for (int pre = 0; pre < 2; pre++) {
        #pragma unroll
        for (int p = 0; p < 2; p++) {
            int idx = tid + p * 256;
            int col = idx >> 2, seg = idx & 3;
            cp16(sb + B_OFF(pre) + col * 80 + seg * 16,
                 &g_hT[(size_t)col * N_NODES + pre * KC + seg * 8]);
        }
        asm volatile("cp.async.commit_group;" ::: "memory");
    }

    for (int c = 0; c < NCHUNK; c++) {
        int ba = c & 1;
        int bb = c % 3;
        // ---- build A tile (fp16 w') + z/r ----
        #pragma unroll
        for (int k = 0; k < 4; k++) {
            uint32_t bits = __shfl_sync(0xffffffffu, word, k);
            int av = (bits >> lane) & 1;
            float wv = av ? fmaxf(pi[k] * jc.x, jc.y) : 0.f;
            __half hw = __float2half(wv);
            As16[(A_OFF(ba) >> 1) + (wid * 4 + k) * 40 + lane] = hw;
            zp[k] += __half2float(hw);
            rp[k] += av ? jc.z : 0.f;
        }
        // ---- prefetch scalars for chunk c+1 ----
        if (c + 1 < NCHUNK) {
            word = (lane < 4) ? g_ab[(i0 + wid * 4 + lane) * NCHUNK + c + 1] : 0u;
            jc = g_jc[(c + 1) * KC + lane];
        }
        asm volatile("cp.async.wait_group 1;" ::: "memory");   // B(c) landed
        __syncthreads();                                        // A(c) visible
        // ---- issue B(c+2) (or empty group to keep the count moving) ----
        if (c + 2 < NCHUNK) {
            #pragma unroll
            for (int p = 0; p < 2; p++) {
                int idx = tid + p * 256;
                int col = idx >> 2, seg = idx & 3;
                cp16(sb + B_OFF((c + 2) % 3) + col * 80 + seg * 16,
                     &g_hT[(size_t)col * N_NODES + (c + 2) * KC + seg * 8]);
            }
        }
        asm volatile("cp.async.commit_group;" ::: "memory");
        // ---- mma: 2 k-steps of 16 ----
        const uint32_t* A32 = &S32[A_OFF(ba) >> 2];
        const uint32_t* B32 = &S32[B_OFF(bb) >> 2];
        #pragma unroll
        for (int s = 0; s < 2; s++) {
            int k0w = s * 8;
            uint32_t af[4];
            int r0 = mw * 16 + gl;
            af[0] = A32[r0 * 20 + k0w + ql];
            af[1] = A32[(r0 + 8) * 20 + k0w + ql];
            af[2] = A32[r0 * 20 + k0w + ql + 4];
            af[3] = A32[(r0 + 8) * 20 + k0w + ql + 4];
            #pragma unroll
            for (int nt = 0; nt < 4; nt++) {
                int col = nw * 32 + nt * 8 + gl;
                uint32_t bf[2];
                bf[0] = B32[col * 20 + k0w + ql];
                bf[1] = B32[col * 20 + k0w + ql + 4];
                mma16(acc[nt], af, bf);
            }
        }
    }

    // ---- reduce z, r across lanes ----
    #pragma unroll
    for (int k = 0; k < 4; k++) {
        float z = zp[k], r = rp[k];
        #pragma unroll
        for (int off = 16; off; off >>= 1) {
            z += __shfl_xor_sync(0xffffffffu, z, off);
            r += __shfl_xor_sync(0xffffffffu, r, off);
        }
        zp[k] = z; rp[k] = r;
    }
    if (lane == 0) {
        #pragma unroll
        for (int k = 0; k < 4; k++) {
            Zs[wid * 4 + k] = zp[k];
            g_r[i0 + wid * 4 + k] = rp[k];
        }
    }
    __syncthreads();

    // ---- epilogue: divide by z, store ----
    int r0 = mw * 16 + gl;
    float inv0 = 1.0f / Zs[r0];
    float inv1 = 1.0f / Zs[r0 + 8];
    #pragma unroll
    for (int nt = 0; nt < 4; nt++) {
        int col = nw * 32 + nt * 8 + ql * 2;
        float2 v0 = make_float2(acc[nt][0] * inv0, acc[nt][1] * inv0);
        float2 v1 = make_float2(acc[nt][2] * inv1, acc[nt][3] * inv1);
        *(float2*)&hp[(size_t)(i0 + r0) * F_DIM + col] = v0;
        *(float2*)&hp[(size_t)(i0 + r0 + 8) * F_DIM + col] = v1;
    }
}

// ===================== Kernel 5: out = elu(r^T @ x) =====================
__global__ void out_kernel(const float* __restrict__ x, float* __restrict__ out) {
    int f = blockIdx.x;
    float p = 0.f;
    for (int i = threadIdx.x; i < N_NODES; i += 256)
        p += g_r[i] * x[(size_t)i * F_DIM + f];
    #pragma unroll
    for (int off = 16; off; off >>= 1)
        p += __shfl_xor_sync(0xffffffffu, p, off);
    __shared__ float s[8];
    int lane = threadIdx.x & 31, wid = threadIdx.x >> 5;
    if (lane == 0) s[wid] = p;
    __syncthreads();
    if (threadIdx.x == 0) {
        float v = 0.f;
        #pragma unroll
        for (int k = 0; k < 8; k++) v += s[k];
        out[f] = (v > 0.f) ? v : (expf(v) - 1.0f);
    }
}

// ===========================================================================
extern "C" void kernel_launch(void* const* d_in, const int* in_sizes, int n_in,
                              void* d_out, int out_size) {
    const float* x   = (const float*)d_in[0];
    const int*   adj = (const int*)  d_in[1];
    const float* W   = (const float*)d_in[2];
    const float* a   = (const float*)d_in[3];
    const float* W2  = (const float*)d_in[4];
    float* out = (float*)d_out;   // [0:128) elu output, [128:) h_prime

    cudaFuncSetAttribute(attn_kernel, cudaFuncAttributeMaxDynamicSharedMemorySize, DYN_SMEM);

    prep_kernel<<<N_NODES / 8, 256>>>(x, W, a, W2);
    pack_kernel<<<N_NODES / 8, 256>>>(adj);
    transpose_kernel<<<dim3(N_NODES / 32, F_DIM / 32), 256>>>();
    attn_kernel<<<N_NODES / M_CTA, 256, DYN_SMEM>>>(out + F_DIM);
    out_kernel<<<F_DIM, 256>>>(x, out);
}

// round 7
// speedup vs baseline: 3.7337x; 1.2316x over previous
#include <cuda_runtime.h>
#include <cuda_fp16.h>
#include <cstdint>
#include <cstddef>

#define N_NODES 8192
#define F_DIM   128
#define KC      32
#define KSPLIT  4
#define JSPAN   (N_NODES / KSPLIT)   // 2048
#define CHUNKS  (JSPAN / KC)         // 64
#define M_CTA   64

// smem bytes: A[2][64][40]h = 10240, B[3][128][40]h = 30720
#define A_OFF(b)  ((b) * 5120)
#define B_OFF(b)  (10240 + (b) * 10240)
#define DYN_SMEM  40960

// ---- scratch ----
__device__ float  g_h   [N_NODES * F_DIM];
__device__ __half g_hT  [(size_t)F_DIM * N_NODES];      // h fp16 transposed [f][j]
__device__ float  g_q   [N_NODES];                      // exp(0.8*f1)
__device__ float4 g_jc  [N_NODES];                      // {exp(f2), exp(0.2*f2), W2, 0}
__device__ float  g_part[KSPLIT][N_NODES * F_DIM];      // partial numerators
__device__ float  g_z   [KSPLIT][N_NODES];              // partial z
__device__ float  g_rp  [KSPLIT][N_NODES];              // partial r

// ===================== helpers =====================
__device__ __forceinline__ uint32_t smem_u32(const void* p) {
    uint32_t a;
    asm("{ .reg .u64 t; cvta.to.shared.u64 t, %1; cvt.u32.u64 %0, t; }" : "=r"(a) : "l"(p));
    return a;
}
__device__ __forceinline__ void mma16(float* d, const uint32_t* a, const uint32_t* b) {
    asm volatile("mma.sync.aligned.m16n8k16.row.col.f32.f16.f16.f32 "
        "{%0,%1,%2,%3}, {%4,%5,%6,%7}, {%8,%9}, {%0,%1,%2,%3};"
        : "+f"(d[0]), "+f"(d[1]), "+f"(d[2]), "+f"(d[3])
        : "r"(a[0]), "r"(a[1]), "r"(a[2]), "r"(a[3]), "r"(b[0]), "r"(b[1]));
}
__device__ __forceinline__ void cp16(uint32_t daddr, const void* gsrc) {
    asm volatile("cp.async.cg.shared.global [%0], [%1], 16;"
                 :: "r"(daddr), "l"(gsrc) : "memory");
}

// ===================== Kernel 1: prep =====================
__global__ __launch_bounds__(256) void prep_kernel(const float* __restrict__ x,
                                                   const float* __restrict__ W,
                                                   const float* __restrict__ a,
                                                   const float* __restrict__ W2) {
    int wid = threadIdx.x >> 5, lane = threadIdx.x & 31;
    int i = blockIdx.x * 8 + wid;
    float4 xv = *(const float4*)&x[(size_t)i * F_DIM + lane * 4];
    float4 wv = *(const float4*)&W[(size_t)i * F_DIM + lane * 4];
    float4 h;
    h.x = xv.x * wv.x; h.y = xv.y * wv.y; h.z = xv.z * wv.z; h.w = xv.w * wv.w;
    *(float4*)&g_h[(size_t)i * F_DIM + lane * 4] = h;

    float4 a1 = *(const float4*)&a[lane * 4];
    float4 a2 = *(const float4*)&a[F_DIM + lane * 4];
    float p1 = h.x * a1.x + h.y * a1.y + h.z * a1.z + h.w * a1.w;
    float p2 = h.x * a2.x + h.y * a2.y + h.z * a2.z + h.w * a2.w;
    #pragma unroll
    for (int off = 16; off; off >>= 1) {
        p1 += __shfl_xor_sync(0xffffffffu, p1, off);
        p2 += __shfl_xor_sync(0xffffffffu, p2, off);
    }
    if (lane == 0) {
        g_q[i] = expf(0.8f * p1);
        float4 jc;
        jc.x = expf(p2);
        jc.y = expf(0.2f * p2);
        jc.z = W2[i];
        jc.w = 0.f;
        g_jc[i] = jc;
    }
}

// ===================== Kernel 2: transpose + fp16 convert =====================
__global__ __launch_bounds__(256) void transpose_kernel() {
    __shared__ float t[32][33];
    int j0 = blockIdx.x * 32, f0 = blockIdx.y * 32;
    int tx = threadIdx.x & 31, ty = threadIdx.x >> 5;
    #pragma unroll
    for (int k = 0; k < 4; k++)
        t[ty + k * 8][tx] = g_h[(size_t)(j0 + ty + k * 8) * F_DIM + f0 + tx];
    __syncthreads();
    #pragma unroll
    for (int k = 0; k < 4; k++)
        g_hT[(size_t)(f0 + ty + k * 8) * N_NODES + j0 + tx] = __float2half(t[tx][ty + k * 8]);
}

// ===================== Kernel 3: split-K fp16 mma attention =====================
// grid (128, 4): blockIdx.x = i-block (64 rows), blockIdx.y = j-split (2048 cols).
// 256 threads / 8 warps; warp tile 32x32: mw = wid&1, nw = wid>>1.
__global__ __launch_bounds__(256, 2) void attn_kernel(const int* __restrict__ adj) {
    extern __shared__ char smc[];
    uint32_t sb = smem_u32(smc);
    __half*   As16 = (__half*)smc;
    uint32_t* S32  = (uint32_t*)smc;

    int tid = threadIdx.x, wid = tid >> 5, lane = tid & 31;
    int gl = lane >> 2, ql = lane & 3;
    int i0 = blockIdx.x * M_CTA;
    int split = blockIdx.y;
    int jbase = split * JSPAN;
    int mw = wid & 1, nw = wid >> 1;

    // build state: warp owns rows wid*8 .. +7, lane = j within chunk
    float pi[8], zp[8], rp[8];
    const int* ap = adj + (size_t)(i0 + wid * 8) * N_NODES + jbase + lane;
    #pragma unroll
    for (int k = 0; k < 8; k++) {
        pi[k] = g_q[i0 + wid * 8 + k];
        zp[k] = 0.f; rp[k] = 0.f;
    }

    float acc[2][4][4];
    #pragma unroll
    for (int mt = 0; mt < 2; mt++)
        #pragma unroll
        for (int nt = 0; nt < 4; nt++)
            acc[mt][nt][0] = acc[mt][nt][1] = acc[mt][nt][2] = acc[mt][nt][3] = 0.f;

    // ---- prologue: chunk-0 scalars, B0/B1 in flight ----
    int av[8];
    float4 jc = g_jc[jbase + lane];
    #pragma unroll
    for (int k = 0; k < 8; k++) av[k] = __ldcs(ap + (size_t)k * N_NODES);
    #pragma unroll
    for (int pre = 0; pre < 2; pre++) {
        #pragma unroll
        for (int p = 0; p < 2; p++) {
            int idx = tid + p * 256;
            int col = idx >> 2, seg = idx & 3;
            cp16(sb + B_OFF(pre) + col * 80 + seg * 16,
                 &g_hT[(size_t)col * N_NODES + jbase + pre * KC + seg * 8]);
        }
        asm volatile("cp.async.commit_group;" ::: "memory");
    }

    for (int c = 0; c < CHUNKS; c++) {
        int ba = c & 1;
        int bb = c % 3;
        // ---- build A tile (fp16 w') + z/r ----
        #pragma unroll
        for (int k = 0; k < 8; k++) {
            float wv = av[k] ? fmaxf(pi[k] * jc.x, jc.y) : 0.f;
            __half hw = __float2half(wv);
            As16[(A_OFF(ba) >> 1) + (wid * 8 + k) * 40 + lane] = hw;
            zp[k] += __half2float(hw);
            rp[k] += av[k] ? jc.z : 0.f;
        }
        // ---- prefetch scalars for chunk c+1 ----
        if (c + 1 < CHUNKS) {
            jc = g_jc[jbase + (c + 1) * KC + lane];
            const int* ap2 = ap + (c + 1) * KC;
            #pragma unroll
            for (int k = 0; k < 8; k++) av[k] = __ldcs(ap2 + (size_t)k * N_NODES);
        }
        asm volatile("cp.async.wait_group 1;" ::: "memory");   // B(c) landed
        __syncthreads();                                        // A(c) visible
        // ---- issue B(c+2) ----
        if (c + 2 < CHUNKS) {
            #pragma unroll
            for (int p = 0; p < 2; p++) {
                int idx = tid + p * 256;
                int col = idx >> 2, seg = idx & 3;
                cp16(sb + B_OFF((c + 2) % 3) + col * 80 + seg * 16,
                     &g_hT[(size_t)col * N_NODES + jbase + (c + 2) * KC + seg * 8]);
            }
        }
        asm volatile("cp.async.commit_group;" ::: "memory");
        // ---- mma: 2 k16 steps, warp tile 32x32 ----
        const uint32_t* A32 = &S32[A_OFF(ba) >> 2];
        const uint32_t* B32 = &S32[B_OFF(bb) >> 2];
        #pragma unroll
        for (int s = 0; s < 2; s++) {
            int k0w = s * 8;
            uint32_t af[2][4];
            #pragma unroll
            for (int mt = 0; mt < 2; mt++) {
                int r0 = mw * 32 + mt * 16 + gl;
                af[mt][0] = A32[r0 * 20 + k0w + ql];
                af[mt][1] = A32[(r0 + 8) * 20 + k0w + ql];
                af[mt][2] = A32[r0 * 20 + k0w + ql + 4];
                af[mt][3] = A32[(r0 + 8) * 20 + k0w + ql + 4];
            }
            #pragma unroll
            for (int nt = 0; nt < 4; nt++) {
                int col = nw * 32 + nt * 8 + gl;
                uint32_t bf[2];
                bf[0] = B32[col * 20 + k0w + ql];
                bf[1] = B32[col * 20 + k0w + ql + 4];
                mma16(acc[0][nt], af[0], bf);
                mma16(acc[1][nt], af[1], bf);
            }
        }
    }

    // ---- reduce z, r across lanes; write partials ----
    #pragma unroll
    for (int k = 0; k < 8; k++) {
        float z = zp[k], r = rp[k];
        #pragma unroll
        for (int off = 16; off; off >>= 1) {
            z += __shfl_xor_sync(0xffffffffu, z, off);
            r += __shfl_xor_sync(0xffffffffu, r, off);
        }
        zp[k] = z; rp[k] = r;
    }
    if (lane == 0) {
        #pragma unroll
        for (int k = 0; k < 8; k++) {
            g_z [split][i0 + wid * 8 + k] = zp[k];
            g_rp[split][i0 + wid * 8 + k] = rp[k];
        }
    }

    // ---- write partial numerators (no division) ----
    float* part = g_part[split];
    #pragma unroll
    for (int mt = 0; mt < 2; mt++) {
        int r0 = mw * 32 + mt * 16 + gl;
        #pragma unroll
        for (int nt = 0; nt < 4; nt++) {
            int col = nw * 32 + nt * 8 + ql * 2;
            *(float2*)&part[(size_t)(i0 + r0) * F_DIM + col] =
                make_float2(acc[mt][nt][0], acc[mt][nt][1]);
            *(float2*)&part[(size_t)(i0 + r0 + 8) * F_DIM + col] =
                make_float2(acc[mt][nt][2], acc[mt][nt][3]);
        }
    }
}

// ===================== Kernel 4: combine partials =====================
__global__ __launch_bounds__(256) void combine_kernel(float* __restrict__ hp) {
    int idx = blockIdx.x * 256 + threadIdx.x;   // float4 index, 262144 total
    int i = idx >> 5;                            // 32 float4 per row
    float z = g_z[0][i] + g_z[1][i] + g_z[2][i] + g_z[3][i];
    float inv = 1.0f / z;
    float4 s0 = ((const float4*)g_part[0])[idx];
    float4 s1 = ((const float4*)g_part[1])[idx];
    float4 s2 = ((const float4*)g_part[2])[idx];
    float4 s3 = ((const float4*)g_part[3])[idx];
    float4 o;
    o.x = (s0.x + s1.x + s2.x + s3.x) * inv;
    o.y = (s0.y + s1.y + s2.y + s3.y) * inv;
    o.z = (s0.z + s1.z + s2.z + s3.z) * inv;
    o.w = (s0.w + s1.w + s2.w + s3.w) * inv;
    ((float4*)hp)[idx] = o;
}

// ===================== Kernel 5: out = elu(r^T @ x) =====================
__global__ void out_kernel(const float* __restrict__ x, float* __restrict__ out) {
    int f = blockIdx.x;
    float p = 0.f;
    for (int i = threadIdx.x; i < N_NODES; i += 256) {
        float r = g_rp[0][i] + g_rp[1][i] + g_rp[2][i] + g_rp[3][i];
        p += r * x[(size_t)i * F_DIM + f];
    }
    #pragma unroll
    for (int off = 16; off; off >>= 1)
        p += __shfl_xor_sync(0xffffffffu, p, off);
    __shared__ float s[8];
    int lane = threadIdx.x & 31, wid = threadIdx.x >> 5;
    if (lane == 0) s[wid] = p;
    __syncthreads();
    if (threadIdx.x == 0) {
        float v = 0.f;
        #pragma unroll
        for (int k = 0; k < 8; k++) v += s[k];
        out[f] = (v > 0.f) ? v : (expf(v) - 1.0f);
    }
}

// ===========================================================================
extern "C" void kernel_launch(void* const* d_in, const int* in_sizes, int n_in,
                              void* d_out, int out_size) {
    const float* x   = (const float*)d_in[0];
    const int*   adj = (const int*)  d_in[1];
    const float* W   = (const float*)d_in[2];
    const float* a   = (const float*)d_in[3];
    const float* W2  = (const float*)d_in[4];
    float* out = (float*)d_out;   // [0:128) elu output, [128:) h_prime

    cudaFuncSetAttribute(attn_kernel, cudaFuncAttributeMaxDynamicSharedMemorySize, DYN_SMEM);

    prep_kernel<<<N_NODES / 8, 256>>>(x, W, a, W2);
    transpose_kernel<<<dim3(N_NODES / 32, F_DIM / 32), 256>>>();
    attn_kernel<<<dim3(N_NODES / M_CTA, KSPLIT), 256, DYN_SMEM>>>(adj);
    combine_kernel<<<(N_NODES * F_DIM / 4) / 256, 256>>>(out + F_DIM);
    out_kernel<<<F_DIM, 256>>>(x, out);
}

// round 8
// speedup vs baseline: 4.8470x; 1.2982x over previous
#include <cuda_runtime.h>
#include <cuda_fp16.h>
#include <cstdint>
#include <cstddef>

#define N_NODES 8192
#define F_DIM   128
#define KC      64
#define KSPLIT  4
#define JSPAN   (N_NODES / KSPLIT)   // 2048
#define CHUNKS  (JSPAN / KC)         // 32
#define M_CTA   64

// smem bytes: A[2][64][72]h (stride 144B), B[2][128][72]h
#define A_OFF(b)  ((b) * 9216)
#define B_OFF(b)  (18432 + (b) * 18432)
#define DYN_SMEM  55296

// ---- scratch ----
__device__ float  g_h   [N_NODES * F_DIM];
__device__ __half g_hT  [(size_t)F_DIM * N_NODES];      // h fp16 transposed [f][j]
__device__ float  g_q   [N_NODES];                      // exp(0.8*f1)
__device__ float4 g_jc  [N_NODES];                      // {exp(f2), exp(0.2*f2), W2, 0}
__device__ float  g_part[KSPLIT][N_NODES * F_DIM];      // partial numerators
__device__ float  g_z   [KSPLIT][N_NODES];              // partial z
__device__ float  g_rp  [KSPLIT][N_NODES];              // partial r

// ===================== helpers =====================
__device__ __forceinline__ uint32_t smem_u32(const void* p) {
    uint32_t a;
    asm("{ .reg .u64 t; cvta.to.shared.u64 t, %1; cvt.u32.u64 %0, t; }" : "=r"(a) : "l"(p));
    return a;
}
__device__ __forceinline__ void mma16(float* d, const uint32_t* a, uint32_t b0, uint32_t b1) {
    asm volatile("mma.sync.aligned.m16n8k16.row.col.f32.f16.f16.f32 "
        "{%0,%1,%2,%3}, {%4,%5,%6,%7}, {%8,%9}, {%0,%1,%2,%3};"
        : "+f"(d[0]), "+f"(d[1]), "+f"(d[2]), "+f"(d[3])
        : "r"(a[0]), "r"(a[1]), "r"(a[2]), "r"(a[3]), "r"(b0), "r"(b1));
}
__device__ __forceinline__ void ldsm4(uint32_t* r, uint32_t addr) {
    asm volatile("ldmatrix.sync.aligned.m8n8.x4.shared.b16 {%0,%1,%2,%3}, [%4];"
        : "=r"(r[0]), "=r"(r[1]), "=r"(r[2]), "=r"(r[3]) : "r"(addr));
}
__device__ __forceinline__ void cp16(uint32_t daddr, const void* gsrc) {
    asm volatile("cp.async.cg.shared.global [%0], [%1], 16;"
                 :: "r"(daddr), "l"(gsrc) : "memory");
}

// ===================== Kernel 1: prep =====================
__global__ __launch_bounds__(256) void prep_kernel(const float* __restrict__ x,
                                                   const float* __restrict__ W,
                                                   const float* __restrict__ a,
                                                   const float* __restrict__ W2) {
    int wid = threadIdx.x >> 5, lane = threadIdx.x & 31;
    int i = blockIdx.x * 8 + wid;
    float4 xv = *(const float4*)&x[(size_t)i * F_DIM + lane * 4];
    float4 wv = *(const float4*)&W[(size_t)i * F_DIM + lane * 4];
    float4 h;
    h.x = xv.x * wv.x; h.y = xv.y * wv.y; h.z = xv.z * wv.z; h.w = xv.w * wv.w;
    *(float4*)&g_h[(size_t)i * F_DIM + lane * 4] = h;

    float4 a1 = *(const float4*)&a[lane * 4];
    float4 a2 = *(const float4*)&a[F_DIM + lane * 4];
    float p1 = h.x * a1.x + h.y * a1.y + h.z * a1.z + h.w * a1.w;
    float p2 = h.x * a2.x + h.y * a2.y + h.z * a2.z + h.w * a2.w;
    #pragma unroll
    for (int off = 16; off; off >>= 1) {
        p1 += __shfl_xor_sync(0xffffffffu, p1, off);
        p2 += __shfl_xor_sync(0xffffffffu, p2, off);
    }
    if (lane == 0) {
        g_q[i] = expf(0.8f * p1);
        float4 jc;
        jc.x = expf(p2);
        jc.y = expf(0.2f * p2);
        jc.z = W2[i];
        jc.w = 0.f;
        g_jc[i] = jc;
    }
}

// ===================== Kernel 2: transpose + fp16 convert =====================
__global__ __launch_bounds__(256) void transpose_kernel() {
    __shared__ float t[32][33];
    int j0 = blockIdx.x * 32, f0 = blockIdx.y * 32;
    int tx = threadIdx.x & 31, ty = threadIdx.x >> 5;
    #pragma unroll
    for (int k = 0; k < 4; k++)
        t[ty + k * 8][tx] = g_h[(size_t)(j0 + ty + k * 8) * F_DIM + f0 + tx];
    __syncthreads();
    #pragma unroll
    for (int k = 0; k < 4; k++)
        g_hT[(size_t)(f0 + ty + k * 8) * N_NODES + j0 + tx] = __float2half(t[tx][ty + k * 8]);
}

// ===================== Kernel 3: split-K fp16 mma attention =====================
// grid (128, 4): x = i-block (64 rows), y = j-split (2048 cols).
// 256 threads / 8 warps; warp tile 32x32: mw = wid&1, nw = wid>>1.
__global__ __launch_bounds__(256, 2) void attn_kernel(const int* __restrict__ adj) {
    extern __shared__ char smc[];
    uint32_t sb = smem_u32(smc);

    int tid = threadIdx.x, wid = tid >> 5, lane = tid & 31;
    int i0 = blockIdx.x * M_CTA;
    int split = blockIdx.y;
    int jbase = split * JSPAN;
    int mw = wid & 1, nw = wid >> 1;

    // ldmatrix per-lane offsets
    uint32_t offA = (uint32_t)(lane & 15) * 144u + (uint32_t)(lane & 16);
    uint32_t offB = ((uint32_t)(lane & 7) + ((uint32_t)(lane & 16) >> 1)) * 144u
                  + ((uint32_t)(lane & 8) << 1);

    // build state: warp owns rows wid*8..+7; lane owns j pair (2*lane, 2*lane+1)
    float pi[8], zp[8], rp[8];
    const int* ap = adj + (size_t)(i0 + wid * 8) * N_NODES + jbase + 2 * lane;
    #pragma unroll
    for (int k = 0; k < 8; k++) {
        pi[k] = g_q[i0 + wid * 8 + k];
        zp[k] = 0.f; rp[k] = 0.f;
    }

    float acc[2][4][4];
    #pragma unroll
    for (int mt = 0; mt < 2; mt++)
        #pragma unroll
        for (int nt = 0; nt < 4; nt++)
            acc[mt][nt][0] = acc[mt][nt][1] = acc[mt][nt][2] = acc[mt][nt][3] = 0.f;

    // ---- prologue: chunk-0 scalars + B(0) in flight ----
    int2 av[8];
    float4 jcA = g_jc[jbase + 2 * lane];
    float4 jcB = g_jc[jbase + 2 * lane + 1];
    #pragma unroll
    for (int k = 0; k < 8; k++) av[k] = __ldcs((const int2*)(ap + (size_t)k * N_NODES));
    #pragma unroll
    for (int p = 0; p < 4; p++) {
        int idx = tid + p * 256;
        int col = idx >> 3, seg = idx & 7;
        cp16(sb + B_OFF(0) + col * 144 + seg * 16,
             &g_hT[(size_t)col * N_NODES + jbase + seg * 8]);
    }
    asm volatile("cp.async.commit_group;" ::: "memory");

    for (int c = 0; c < CHUNKS; c++) {
        int bu = c & 1;
        // ---- build A tile (fp16 w' pairs) + z/r ----
        #pragma unroll
        for (int k = 0; k < 8; k++) {
            float w0 = av[k].x ? fmaxf(pi[k] * jcA.x, jcA.y) : 0.f;
            float w1 = av[k].y ? fmaxf(pi[k] * jcB.x, jcB.y) : 0.f;
            __half2 hw = __floats2half2_rn(w0, w1);
            *(__half2*)(smc + A_OFF(bu) + (wid * 8 + k) * 144 + lane * 4) = hw;
            zp[k] += __low2float(hw) + __high2float(hw);
            rp[k] += (av[k].x ? jcA.z : 0.f) + (av[k].y ? jcB.z : 0.f);
        }
        // ---- prefetch scalars for chunk c+1 ----
        if (c + 1 < CHUNKS) {
            jcA = g_jc[jbase + (c + 1) * KC + 2 * lane];
            jcB = g_jc[jbase + (c + 1) * KC + 2 * lane + 1];
            const int* ap2 = ap + (c + 1) * KC;
            #pragma unroll
            for (int k = 0; k < 8; k++)
                av[k] = __ldcs((const int2*)(ap2 + (size_t)k * N_NODES));
        }
        asm volatile("cp.async.wait_group 0;" ::: "memory");   // B(c) landed
        __syncthreads();                                        // A(c) visible
        // ---- issue B(c+1) into other buffer (overlaps mma) ----
        if (c + 1 < CHUNKS) {
            #pragma unroll
            for (int p = 0; p < 4; p++) {
                int idx = tid + p * 256;
                int col = idx >> 3, seg = idx & 7;
                cp16(sb + B_OFF(bu ^ 1) + col * 144 + seg * 16,
                     &g_hT[(size_t)col * N_NODES + jbase + (c + 1) * KC + seg * 8]);
            }
            asm volatile("cp.async.commit_group;" ::: "memory");
        }
        // ---- mma: 4 k16 steps, warp tile 32x32, LDSM fragments ----
        uint32_t Ab = sb + A_OFF(bu) + (mw * 32) * 144 + offA;
        uint32_t Bb = sb + B_OFF(bu) + (nw * 32) * 144 + offB;
        #pragma unroll
        for (int s = 0; s < 4; s++) {
            uint32_t af[2][4], bq0[4], bq1[4];
            ldsm4(af[0], Ab + s * 32);
            ldsm4(af[1], Ab + 16 * 144 + s * 32);
            ldsm4(bq0, Bb + s * 32);
            ldsm4(bq1, Bb + 16 * 144 + s * 32);
            #pragma unroll
            for (int mt = 0; mt < 2; mt++) {
                mma16(acc[mt][0], af[mt], bq0[0], bq0[1]);
                mma16(acc[mt][1], af[mt], bq0[2], bq0[3]);
                mma16(acc[mt][2], af[mt], bq1[0], bq1[1]);
                mma16(acc[mt][3], af[mt], bq1[2], bq1[3]);
            }
        }
    }

    // ---- reduce z, r across lanes; write split partials ----
    #pragma unroll
    for (int k = 0; k < 8; k++) {
        float z = zp[k], r = rp[k];
        #pragma unroll
        for (int off = 16; off; off >>= 1) {
            z += __shfl_xor_sync(0xffffffffu, z, off);
            r += __shfl_xor_sync(0xffffffffu, r, off);
        }
        zp[k] = z; rp[k] = r;
    }
    if (lane == 0) {
        #pragma unroll
        for (int k = 0; k < 8; k++) {
            g_z [split][i0 + wid * 8 + k] = zp[k];
            g_rp[split][i0 + wid * 8 + k] = rp[k];
        }
    }

    // ---- write partial numerators ----
    int gl = lane >> 2, ql = lane & 3;
    float* part = g_part[split];
    #pragma unroll
    for (int mt = 0; mt < 2; mt++) {
        int r0 = mw * 32 + mt * 16 + gl;
        #pragma unroll
        for (int nt = 0; nt < 4; nt++) {
            int col = nw * 32 + nt * 8 + ql * 2;
            *(float2*)&part[(size_t)(i0 + r0) * F_DIM + col] =
                make_float2(acc[mt][nt][0], acc[mt][nt][1]);
            *(float2*)&part[(size_t)(i0 + r0 + 8) * F_DIM + col] =
                make_float2(acc[mt][nt][2], acc[mt][nt][3]);
        }
    }
}

// ===================== Kernel 4: combine partials =====================
__global__ __launch_bounds__(256) void combine_kernel(float* __restrict__ hp) {
    int idx = blockIdx.x * 256 + threadIdx.x;   // float4 index
    int i = idx >> 5;
    float z = g_z[0][i] + g_z[1][i] + g_z[2][i] + g_z[3][i];
    float inv = 1.0f / z;
    float4 s0 = ((const float4*)g_part[0])[idx];
    float4 s1 = ((const float4*)g_part[1])[idx];
    float4 s2 = ((const float4*)g_part[2])[idx];
    float4 s3 = ((const float4*)g_part[3])[idx];
    float4 o;
    o.x = (s0.x + s1.x + s2.x + s3.x) * inv;
    o.y = (s0.y + s1.y + s2.y + s3.y) * inv;
    o.z = (s0.z + s1.z + s2.z + s3.z) * inv;
    o.w = (s0.w + s1.w + s2.w + s3.w) * inv;
    ((float4*)hp)[idx] = o;
}

// ===================== Kernel 5: out = elu(r^T @ x) =====================
__global__ void out_kernel(const float* __restrict__ x, float* __restrict__ out) {
    int f = blockIdx.x;
    float p = 0.f;
    for (int i = threadIdx.x; i < N_NODES; i += 256) {
        float r = g_rp[0][i] + g_rp[1][i] + g_rp[2][i] + g_rp[3][i];
        p += r * x[(size_t)i * F_DIM + f];
    }
    #pragma unroll
    for (int off = 16; off; off >>= 1)
        p += __shfl_xor_sync(0xffffffffu, p, off);
    __shared__ float s[8];
    int lane = threadIdx.x & 31, wid = threadIdx.x >> 5;
    if (lane == 0) s[wid] = p;
    __syncthreads();
    if (threadIdx.x == 0) {
        float v = 0.f;
        #pragma unroll
        for (int k = 0; k < 8; k++) v += s[k];
        out[f] = (v > 0.f) ? v : (expf(v) - 1.0f);
    }
}

// ===========================================================================
extern "C" void kernel_launch(void* const* d_in, const int* in_sizes, int n_in,
                              void* d_out, int out_size) {
    const float* x   = (const float*)d_in[0];
    const int*   adj = (const int*)  d_in[1];
    const float* W   = (const float*)d_in[2];
    const float* a   = (const float*)d_in[3];
    const float* W2  = (const float*)d_in[4];
    float* out = (float*)d_out;   // [0:128) elu output, [128:) h_prime

    cudaFuncSetAttribute(attn_kernel, cudaFuncAttributeMaxDynamicSharedMemorySize, DYN_SMEM);

    prep_kernel<<<N_NODES / 8, 256>>>(x, W, a, W2);
    transpose_kernel<<<dim3(N_NODES / 32, F_DIM / 32), 256>>>();
    attn_kernel<<<dim3(N_NODES / M_CTA, KSPLIT), 256, DYN_SMEM>>>(adj);
    combine_kernel<<<(N_NODES * F_DIM / 4) / 256, 256>>>(out + F_DIM);
    out_kernel<<<F_DIM, 256>>>(x, out);
}